// round 1
// baseline (speedup 1.0000x reference)
#include <cuda_runtime.h>
#include <cstdint>

#define N_NODES 100000
#define N_EDGES 1600000
#define CH 128          // IN_CH = HEADS*HID = OUT_CH = 128
#define HEADS 4
#define HID 32
#define NEG_SLOPE 0.2f

// ---------------- scratch (static device globals; no allocation) ----------------
__device__ float g_h[(size_t)N_NODES * CH];       // x @ W            (51.2 MB)
__device__ float g_accum[(size_t)N_NODES * CH];   // sum ex * h[src]  (51.2 MB)
__device__ float g_asrc[(size_t)N_NODES * HEADS];
__device__ float g_adst[(size_t)N_NODES * HEADS];
__device__ float g_s[(size_t)N_NODES * HEADS];    // sum ex

// ---------------- helpers ----------------
__device__ __forceinline__ void red_add_v4(float* p, float4 v) {
    asm volatile("red.global.add.v4.f32 [%0], {%1,%2,%3,%4};"
                 :: "l"(p), "f"(v.x), "f"(v.y), "f"(v.z), "f"(v.w) : "memory");
}

// ---------------- zero accum + s ----------------
__global__ void zero_kernel() {
    int i = blockIdx.x * blockDim.x + threadIdx.x;
    int stride = gridDim.x * blockDim.x;
    float4 z = make_float4(0.f, 0.f, 0.f, 0.f);
    float4* acc4 = reinterpret_cast<float4*>(g_accum);
    float4* s4   = reinterpret_cast<float4*>(g_s);
    const int nAcc4 = N_NODES * (CH / 4);   // 3.2M
    const int nS4   = N_NODES;              // 100K (HEADS=4 floats -> 1 float4/node)
    for (int j = i; j < nAcc4; j += stride) acc4[j] = z;
    for (int j = i; j < nS4;   j += stride) s4[j]   = z;
}

// ---------------- GEMM: C[M,128] = A[M,128] @ B[128,128] ----------------
// SCALE_A: multiply A element by 1/(s[row, k/32]+1e-16) at load (alpha normalize)
// EPILOG : add bias + ReLU
template<bool SCALE_A, bool EPILOG>
__global__ void __launch_bounds__(256) gemm128(
    const float* __restrict__ A, const float* __restrict__ B,
    const float* __restrict__ bias, float* __restrict__ C, int M)
{
    __shared__ float Xs[64][32];
    __shared__ float Ws[32][128];

    const int tid = threadIdx.x;
    const int tx = tid & 31;       // column group: cols [4*tx, 4*tx+4)
    const int ty = tid >> 5;       // row group: rows [8*ty, 8*ty+8) within tile
    const int row0 = blockIdx.x * 64;

    float acc[8][4];
#pragma unroll
    for (int i = 0; i < 8; ++i)
#pragma unroll
        for (int j = 0; j < 4; ++j) acc[i][j] = 0.f;

#pragma unroll
    for (int kc = 0; kc < 4; ++kc) {
        // load A tile [64 rows][32 k] as float4s
#pragma unroll
        for (int q = 0; q < 2; ++q) {
            int f = tid + q * 256;          // [0,512)
            int r = f >> 3, c4 = f & 7;
            int row = row0 + r;
            float4 v = make_float4(0.f, 0.f, 0.f, 0.f);
            if (row < M) {
                v = *reinterpret_cast<const float4*>(&A[(size_t)row * CH + kc * 32 + c4 * 4]);
                if (SCALE_A) {
                    float inv = 1.f / (g_s[(size_t)row * HEADS + kc] + 1e-16f);
                    v.x *= inv; v.y *= inv; v.z *= inv; v.w *= inv;
                }
            }
            *reinterpret_cast<float4*>(&Xs[r][c4 * 4]) = v;
        }
        // load B tile [32 k][128 cols]
#pragma unroll
        for (int q = 0; q < 4; ++q) {
            int f = tid + q * 256;          // [0,1024)
            int r = f >> 5, c4 = f & 31;
            *reinterpret_cast<float4*>(&Ws[r][c4 * 4]) =
                *reinterpret_cast<const float4*>(&B[(size_t)(kc * 32 + r) * CH + c4 * 4]);
        }
        __syncthreads();

#pragma unroll
        for (int k = 0; k < 32; ++k) {
            float4 b4 = *reinterpret_cast<float4*>(&Ws[k][tx * 4]);
            float a[8];
#pragma unroll
            for (int i = 0; i < 8; ++i) a[i] = Xs[ty * 8 + i][k];
#pragma unroll
            for (int i = 0; i < 8; ++i) {
                acc[i][0] = fmaf(a[i], b4.x, acc[i][0]);
                acc[i][1] = fmaf(a[i], b4.y, acc[i][1]);
                acc[i][2] = fmaf(a[i], b4.z, acc[i][2]);
                acc[i][3] = fmaf(a[i], b4.w, acc[i][3]);
            }
        }
        __syncthreads();
    }

    float4 bv = make_float4(0.f, 0.f, 0.f, 0.f);
    if (EPILOG) bv = *reinterpret_cast<const float4*>(&bias[tx * 4]);

#pragma unroll
    for (int i = 0; i < 8; ++i) {
        int row = row0 + ty * 8 + i;
        if (row < M) {
            float4 o;
            o.x = acc[i][0]; o.y = acc[i][1]; o.z = acc[i][2]; o.w = acc[i][3];
            if (EPILOG) {
                o.x = fmaxf(o.x + bv.x, 0.f);
                o.y = fmaxf(o.y + bv.y, 0.f);
                o.z = fmaxf(o.z + bv.z, 0.f);
                o.w = fmaxf(o.w + bv.w, 0.f);
            }
            *reinterpret_cast<float4*>(&C[(size_t)row * CH + tx * 4]) = o;
        }
    }
}

// ---------------- per-node attention logit components ----------------
// a_src[n,h] = sum_c h[n,h*32+c] * att_src[h*32+c]   (flat layout matches)
__global__ void att_kernel(const float* __restrict__ att_s,
                           const float* __restrict__ att_d, int N)
{
    int warp = (blockIdx.x * blockDim.x + threadIdx.x) >> 5;
    if (warp >= N) return;
    int lane = threadIdx.x & 31;

    float4 hv  = *reinterpret_cast<const float4*>(&g_h[(size_t)warp * CH + lane * 4]);
    float4 asv = *reinterpret_cast<const float4*>(&att_s[lane * 4]);
    float4 adv = *reinterpret_cast<const float4*>(&att_d[lane * 4]);

    float ps = hv.x * asv.x + hv.y * asv.y + hv.z * asv.z + hv.w * asv.w;
    float pd = hv.x * adv.x + hv.y * adv.y + hv.z * adv.z + hv.w * adv.w;

    // reduce within 8-lane head groups (head h owns lanes [8h, 8h+8))
    ps += __shfl_xor_sync(0xFFFFFFFFu, ps, 1);
    ps += __shfl_xor_sync(0xFFFFFFFFu, ps, 2);
    ps += __shfl_xor_sync(0xFFFFFFFFu, ps, 4);
    pd += __shfl_xor_sync(0xFFFFFFFFu, pd, 1);
    pd += __shfl_xor_sync(0xFFFFFFFFu, pd, 2);
    pd += __shfl_xor_sync(0xFFFFFFFFu, pd, 4);

    if ((lane & 7) == 0) {
        int h = lane >> 3;
        g_asrc[(size_t)warp * HEADS + h] = ps;
        g_adst[(size_t)warp * HEADS + h] = pd;
    }
}

// ---------------- edge pass: one warp per edge ----------------
// ex[h] = exp(leakyrelu(a_src[src,h] + a_dst[dst,h]))
// g_s[dst,h]      += ex[h]
// g_accum[dst,:]  += ex[head(c)] * h[src,c]
__global__ void __launch_bounds__(256) edge_kernel(const int* __restrict__ ei, int E)
{
    int warp = (blockIdx.x * blockDim.x + threadIdx.x) >> 5;
    if (warp >= E) return;
    int lane = threadIdx.x & 31;

    int src = __ldg(&ei[warp]);
    int dst = __ldg(&ei[E + warp]);

    float4 as = *reinterpret_cast<const float4*>(&g_asrc[(size_t)src * HEADS]);
    float4 ad = *reinterpret_cast<const float4*>(&g_adst[(size_t)dst * HEADS]);

    float e0 = as.x + ad.x, e1 = as.y + ad.y, e2 = as.z + ad.z, e3 = as.w + ad.w;
    e0 = (e0 > 0.f) ? e0 : NEG_SLOPE * e0;
    e1 = (e1 > 0.f) ? e1 : NEG_SLOPE * e1;
    e2 = (e2 > 0.f) ? e2 : NEG_SLOPE * e2;
    e3 = (e3 > 0.f) ? e3 : NEG_SLOPE * e3;
    float x0 = __expf(e0), x1 = __expf(e1), x2 = __expf(e2), x3 = __expf(e3);

    if (lane == 0)
        red_add_v4(&g_s[(size_t)dst * HEADS], make_float4(x0, x1, x2, x3));

    float4 hv = *reinterpret_cast<const float4*>(&g_h[(size_t)src * CH + lane * 4]);
    int head = lane >> 3;
    float m = (head < 2) ? (head == 0 ? x0 : x1) : (head == 2 ? x2 : x3);
    float4 msg = make_float4(hv.x * m, hv.y * m, hv.z * m, hv.w * m);
    red_add_v4(&g_accum[(size_t)dst * CH + lane * 4], msg);
}

// ---------------- launch ----------------
extern "C" void kernel_launch(void* const* d_in, const int* in_sizes, int n_in,
                              void* d_out, int out_size)
{
    const float* x     = (const float*)d_in[0];
    const int*   ei    = (const int*)  d_in[1];
    const float* W     = (const float*)d_in[2];
    const float* att_s = (const float*)d_in[3];
    const float* att_d = (const float*)d_in[4];
    const float* lin_w = (const float*)d_in[5];
    const float* lin_b = (const float*)d_in[6];
    float* out = (float*)d_out;

    int N = in_sizes[0] / CH;    // 100000
    int E = in_sizes[1] / 2;     // 1600000

    void* p_h = nullptr;
    cudaGetSymbolAddress(&p_h, g_h);
    void* p_acc = nullptr;
    cudaGetSymbolAddress(&p_acc, g_accum);

    zero_kernel<<<2048, 256>>>();

    int gemm_blocks = (N + 63) / 64;
    gemm128<false, false><<<gemm_blocks, 256>>>(x, W, nullptr, (float*)p_h, N);

    int att_blocks = (N * 32 + 255) / 256;
    att_kernel<<<att_blocks, 256>>>(att_s, att_d, N);

    int edge_blocks = ((size_t)E * 32 + 255) / 256;
    edge_kernel<<<edge_blocks, 256>>>(ei, E);

    gemm128<true, true><<<gemm_blocks, 256>>>((const float*)p_acc, lin_w, lin_b, out, N);
}

// round 2
// speedup vs baseline: 1.3643x; 1.3643x over previous
#include <cuda_runtime.h>
#include <cstdint>

#define N_NODES 100000
#define N_EDGES 1600000
#define CH 128          // IN_CH = HEADS*HID = OUT_CH = 128
#define HEADS 4
#define HID 32
#define NEG_SLOPE 0.2f
#define SCAN_BS 512

// ---------------- scratch (static device globals; no allocation) ----------------
__device__ float g_h[(size_t)N_NODES * CH];       // x @ W                  (51.2 MB)
__device__ float g_accum[(size_t)N_NODES * CH];   // normalized messages    (51.2 MB)
__device__ float g_asrc[(size_t)N_NODES * HEADS];
__device__ float g_adst[(size_t)N_NODES * HEADS];
__device__ int   g_deg[N_NODES];
__device__ int   g_off[N_NODES];
__device__ int   g_cur[N_NODES];
__device__ int   g_srcs[N_EDGES];
__device__ int   g_bsum[256];

// ---------------- f32x2 helpers (Blackwell packed fp32) ----------------
__device__ __forceinline__ void fma2(unsigned long long& d, unsigned long long a,
                                     unsigned long long b) {
    asm("fma.rn.f32x2 %0, %1, %2, %0;" : "+l"(d) : "l"(a), "l"(b));
}
__device__ __forceinline__ void upk(unsigned long long v, float& x, float& y) {
    asm("mov.b64 {%0,%1}, %2;" : "=f"(x), "=f"(y) : "l"(v));
}

// ---------------- CSR build ----------------
__global__ void zero_deg(int N) {
    int i = blockIdx.x * blockDim.x + threadIdx.x;
    if (i < N) g_deg[i] = 0;
}

__global__ void hist_kernel(const int* __restrict__ ei, int E) {
    int i = blockIdx.x * blockDim.x + threadIdx.x;
    if (i < E) atomicAdd(&g_deg[ei[E + i]], 1);
}

__global__ void scan1(int N) {
    __shared__ int sm[SCAN_BS];
    int t = threadIdx.x;
    int i = blockIdx.x * SCAN_BS + t;
    int v = (i < N) ? g_deg[i] : 0;
    sm[t] = v;
    __syncthreads();
#pragma unroll
    for (int d = 1; d < SCAN_BS; d <<= 1) {
        int t2 = (t >= d) ? sm[t - d] : 0;
        __syncthreads();
        sm[t] += t2;
        __syncthreads();
    }
    int incl = sm[t];
    if (i < N) g_off[i] = incl - v;           // local exclusive
    if (t == SCAN_BS - 1) g_bsum[blockIdx.x] = incl;
}

__global__ void scan2(int NB) {
    __shared__ int sm[256];
    int t = threadIdx.x;
    int v = (t < NB) ? g_bsum[t] : 0;
    sm[t] = v;
    __syncthreads();
#pragma unroll
    for (int d = 1; d < 256; d <<= 1) {
        int t2 = (t >= d) ? sm[t - d] : 0;
        __syncthreads();
        sm[t] += t2;
        __syncthreads();
    }
    if (t < NB) g_bsum[t] = sm[t] - v;        // exclusive block offsets
}

__global__ void scan3(int N) {
    int i = blockIdx.x * blockDim.x + threadIdx.x;
    if (i < N) {
        int o = g_off[i] + g_bsum[i / SCAN_BS];
        g_off[i] = o;
        g_cur[i] = o;
    }
}

__global__ void scatter_kernel(const int* __restrict__ ei, int E) {
    int i = blockIdx.x * blockDim.x + threadIdx.x;
    if (i < E) {
        int dst = ei[E + i];
        int pos = atomicAdd(&g_cur[dst], 1);
        g_srcs[pos] = ei[i];
    }
}

// ---------------- GEMM: C[M,128] = A[M,128] @ B[128,128], f32x2 ----------------
// lane tx owns cols {tx, tx+32, tx+64, tx+96}; warp ty owns rows [8ty, 8ty+8) as 4 pairs
template<bool EPILOG>
__global__ void __launch_bounds__(256) gemm128x2(
    const float* __restrict__ A, const float* __restrict__ B,
    const float* __restrict__ bias, float* __restrict__ C, int M)
{
    __shared__ __align__(16) float Xs[32][66];    // [k][row], pad for STS banks
    __shared__ __align__(16) float Wd[32][256];   // [k][2c+{0,1}] duplicated B

    const int tid = threadIdx.x;
    const int tx = tid & 31;
    const int ty = tid >> 5;
    const int row0 = blockIdx.x * 64;

    unsigned long long acc[4][4];
#pragma unroll
    for (int p = 0; p < 4; ++p)
#pragma unroll
        for (int q = 0; q < 4; ++q) acc[p][q] = 0ull;

#pragma unroll
    for (int kc = 0; kc < 4; ++kc) {
        // A tile -> Xs transposed
#pragma unroll
        for (int u = 0; u < 2; ++u) {
            int f = tid + u * 256;         // [0,512)
            int r = f >> 3, c4 = f & 7;
            int row = row0 + r;
            float4 v = make_float4(0.f, 0.f, 0.f, 0.f);
            if (row < M)
                v = *reinterpret_cast<const float4*>(&A[(size_t)row * CH + kc * 32 + c4 * 4]);
            Xs[c4 * 4 + 0][r] = v.x;
            Xs[c4 * 4 + 1][r] = v.y;
            Xs[c4 * 4 + 2][r] = v.z;
            Xs[c4 * 4 + 3][r] = v.w;
        }
        // B tile -> Wd duplicated
#pragma unroll
        for (int u = 0; u < 4; ++u) {
            int f = tid + u * 256;         // [0,1024)
            int r = f >> 5, c4 = f & 31;
            float4 v = *reinterpret_cast<const float4*>(&B[(size_t)(kc * 32 + r) * CH + c4 * 4]);
            float4 d0 = make_float4(v.x, v.x, v.y, v.y);
            float4 d1 = make_float4(v.z, v.z, v.w, v.w);
            *reinterpret_cast<float4*>(&Wd[r][c4 * 8])     = d0;
            *reinterpret_cast<float4*>(&Wd[r][c4 * 8 + 4]) = d1;
        }
        __syncthreads();

#pragma unroll
        for (int k = 0; k < 32; ++k) {
            unsigned long long a[4], b[4];
#pragma unroll
            for (int p = 0; p < 4; ++p)
                a[p] = *reinterpret_cast<const unsigned long long*>(&Xs[k][ty * 8 + 2 * p]);
#pragma unroll
            for (int q = 0; q < 4; ++q)
                b[q] = *reinterpret_cast<const unsigned long long*>(&Wd[k][2 * tx + 64 * q]);
#pragma unroll
            for (int p = 0; p < 4; ++p)
#pragma unroll
                for (int q = 0; q < 4; ++q)
                    fma2(acc[p][q], a[p], b[q]);
        }
        __syncthreads();
    }

    float bv[4];
    if (EPILOG) {
#pragma unroll
        for (int q = 0; q < 4; ++q) bv[q] = bias[tx + 32 * q];
    }

#pragma unroll
    for (int p = 0; p < 4; ++p) {
        int r0 = row0 + ty * 8 + 2 * p;
#pragma unroll
        for (int q = 0; q < 4; ++q) {
            float lo, hi;
            upk(acc[p][q], lo, hi);
            int col = tx + 32 * q;
            if (EPILOG) {
                lo = fmaxf(lo + bv[q], 0.f);
                hi = fmaxf(hi + bv[q], 0.f);
            }
            if (r0 < M)     C[(size_t)r0 * CH + col]       = lo;
            if (r0 + 1 < M) C[(size_t)(r0 + 1) * CH + col] = hi;
        }
    }
}

// ---------------- per-node attention logit components ----------------
__global__ void att_kernel(const float* __restrict__ att_s,
                           const float* __restrict__ att_d, int N)
{
    int warp = (blockIdx.x * blockDim.x + threadIdx.x) >> 5;
    if (warp >= N) return;
    int lane = threadIdx.x & 31;

    float4 hv  = *reinterpret_cast<const float4*>(&g_h[(size_t)warp * CH + lane * 4]);
    float4 asv = *reinterpret_cast<const float4*>(&att_s[lane * 4]);
    float4 adv = *reinterpret_cast<const float4*>(&att_d[lane * 4]);

    float ps = hv.x * asv.x + hv.y * asv.y + hv.z * asv.z + hv.w * asv.w;
    float pd = hv.x * adv.x + hv.y * adv.y + hv.z * adv.z + hv.w * adv.w;

    ps += __shfl_xor_sync(0xFFFFFFFFu, ps, 1);
    ps += __shfl_xor_sync(0xFFFFFFFFu, ps, 2);
    ps += __shfl_xor_sync(0xFFFFFFFFu, ps, 4);
    pd += __shfl_xor_sync(0xFFFFFFFFu, pd, 1);
    pd += __shfl_xor_sync(0xFFFFFFFFu, pd, 2);
    pd += __shfl_xor_sync(0xFFFFFFFFu, pd, 4);

    if ((lane & 7) == 0) {
        int h = lane >> 3;
        g_asrc[(size_t)warp * HEADS + h] = ps;
        g_adst[(size_t)warp * HEADS + h] = pd;
    }
}

// ---------------- gather: one warp per dst node ----------------
__global__ void __launch_bounds__(256) gather_kernel(int N)
{
    int node = (blockIdx.x * blockDim.x + threadIdx.x) >> 5;
    if (node >= N) return;
    int lane = threadIdx.x & 31;
    int head = lane >> 3;

    int off = g_off[node];
    int deg = g_deg[node];

    float4 ad4 = *reinterpret_cast<const float4*>(&g_adst[(size_t)node * HEADS]);
    float ad_my = (lane & 16) ? ((lane & 8) ? ad4.w : ad4.z)
                              : ((lane & 8) ? ad4.y : ad4.x);

    float a0 = 0.f, a1 = 0.f, a2 = 0.f, a3 = 0.f;
    float s_my = 0.f;

    for (int base = 0; base < deg; base += 32) {
        int idx = 0;
        if (base + lane < deg) idx = g_srcs[off + base + lane];
        int cnt = min(32, deg - base);
        for (int j = 0; j < cnt; ++j) {
            int src = __shfl_sync(0xFFFFFFFFu, idx, j);
            float as_my = __ldg(&g_asrc[(size_t)src * HEADS + head]);
            float eh = as_my + ad_my;
            eh = (eh > 0.f) ? eh : NEG_SLOPE * eh;
            float ex = __expf(eh);
            float4 hv = *reinterpret_cast<const float4*>(&g_h[(size_t)src * CH + lane * 4]);
            a0 = fmaf(ex, hv.x, a0);
            a1 = fmaf(ex, hv.y, a1);
            a2 = fmaf(ex, hv.z, a2);
            a3 = fmaf(ex, hv.w, a3);
            s_my += ex;
        }
    }

    float inv = 1.f / (s_my + 1e-16f);
    float4 o = make_float4(a0 * inv, a1 * inv, a2 * inv, a3 * inv);
    *reinterpret_cast<float4*>(&g_accum[(size_t)node * CH + lane * 4]) = o;
}

// ---------------- launch ----------------
extern "C" void kernel_launch(void* const* d_in, const int* in_sizes, int n_in,
                              void* d_out, int out_size)
{
    const float* x     = (const float*)d_in[0];
    const int*   ei    = (const int*)  d_in[1];
    const float* W     = (const float*)d_in[2];
    const float* att_s = (const float*)d_in[3];
    const float* att_d = (const float*)d_in[4];
    const float* lin_w = (const float*)d_in[5];
    const float* lin_b = (const float*)d_in[6];
    float* out = (float*)d_out;

    int N = in_sizes[0] / CH;    // 100000
    int E = in_sizes[1] / 2;     // 1600000
    int NB = (N + SCAN_BS - 1) / SCAN_BS;

    void* p_h = nullptr;
    cudaGetSymbolAddress(&p_h, g_h);
    void* p_acc = nullptr;
    cudaGetSymbolAddress(&p_acc, g_accum);

    int gemm_blocks = (N + 63) / 64;

    zero_deg<<<(N + 255) / 256, 256>>>(N);
    gemm128x2<false><<<gemm_blocks, 256>>>(x, W, nullptr, (float*)p_h, N);
    att_kernel<<<(N * 32 + 255) / 256, 256>>>(att_s, att_d, N);

    hist_kernel<<<(E + 255) / 256, 256>>>(ei, E);
    scan1<<<NB, SCAN_BS>>>(N);
    scan2<<<1, 256>>>(NB);
    scan3<<<(N + 255) / 256, 256>>>(N);
    scatter_kernel<<<(E + 255) / 256, 256>>>(ei, E);

    gather_kernel<<<(N * 32 + 255) / 256, 256>>>(N);

    gemm128x2<true><<<gemm_blocks, 256>>>((const float*)p_acc, lin_w, lin_b, out, N);
}

// round 4
// speedup vs baseline: 1.3655x; 1.0009x over previous
#include <cuda_runtime.h>
#include <cstdint>

#define N_NODES 100000
#define N_EDGES 1600000
#define CH 128          // IN_CH = HEADS*HID = OUT_CH = 128
#define HEADS 4
#define HID 32
#define NEG_SLOPE 0.2f
#define NBLK 148
#define CBS 1024

// ---------------- scratch (static device globals; no allocation) ----------------
__device__ float g_h[(size_t)N_NODES * CH];       // x @ W                  (51.2 MB)
__device__ float g_accum[(size_t)N_NODES * CH];   // normalized messages    (51.2 MB)
__device__ float g_asrc[(size_t)N_NODES * HEADS];
__device__ float g_adst[(size_t)N_NODES * HEADS];
__device__ int   g_deg[N_NODES];
__device__ int   g_off[N_NODES];
__device__ int   g_cur[N_NODES];
__device__ int   g_srcs[N_EDGES];
__device__ int   g_bsum[NBLK];
__device__ unsigned g_c[8];                        // grid-barrier counters (zero-init)

// ---------------- f32x2 helpers (Blackwell packed fp32) ----------------
__device__ __forceinline__ void fma2(unsigned long long& d, unsigned long long a,
                                     unsigned long long b) {
    asm("fma.rn.f32x2 %0, %1, %2, %0;" : "+l"(d) : "l"(a), "l"(b));
}
__device__ __forceinline__ void upk(unsigned long long v, float& x, float& y) {
    asm("mov.b64 {%0,%1}, %2;" : "=f"(x), "=f"(y) : "l"(v));
}

// ---------------- software grid barrier (co-resident grid of NBLK blocks) ----------------
__device__ __forceinline__ void gbar(int ph) {
    __syncthreads();
    if (threadIdx.x == 0) {
        __threadfence();
        atomicAdd(&g_c[ph], 1u);
        while (*(volatile unsigned*)&g_c[ph] < (unsigned)NBLK) { }
        __threadfence();
    }
    __syncthreads();
}

// ---------------- fused CSR build: zero -> hist -> scan -> scatter ----------------
__global__ void __launch_bounds__(CBS, 1) csr_build(const int* __restrict__ ei, int E, int N)
{
    __shared__ int sm[CBS];
    const int b = blockIdx.x, t = threadIdx.x;
    const int gt = b * CBS + t;
    const int GS = NBLK * CBS;
    const int CHUNK = (N + NBLK - 1) / NBLK;       // 676
    const int base = b * CHUNK;

    // P0: zero degrees
    for (int i = gt; i < N; i += GS) g_deg[i] = 0;
    gbar(0);

    // P1: histogram by dst
    for (int i = gt; i < E; i += GS) atomicAdd(&g_deg[ei[E + i]], 1);
    gbar(1);

    // P2: per-block inclusive scan of this block's CHUNK degrees
    int myv = 0;
    if (t < CHUNK && base + t < N) myv = __ldcg(&g_deg[base + t]);
    sm[t] = myv;
    __syncthreads();
#pragma unroll
    for (int d = 1; d < CBS; d <<= 1) {
        int v2 = (t >= d) ? sm[t - d] : 0;
        __syncthreads();
        sm[t] += v2;
        __syncthreads();
    }
    int incl = sm[t];
    if (t < CHUNK && base + t < N) g_off[base + t] = incl - myv;   // local exclusive
    if (t == CBS - 1) g_bsum[b] = incl;                             // block total
    gbar(2);

    // P3: block 0 scans the NBLK block totals (exclusive)
    if (b == 0) {
        int v = (t < NBLK) ? __ldcg(&g_bsum[t]) : 0;
        sm[t] = v;
        __syncthreads();
#pragma unroll
        for (int d = 1; d < CBS; d <<= 1) {
            int v2 = (t >= d) ? sm[t - d] : 0;
            __syncthreads();
            sm[t] += v2;
            __syncthreads();
        }
        if (t < NBLK) g_bsum[t] = sm[t] - v;
    }
    gbar(3);

    // P4: global offsets
    {
        int boff = __ldcg(&g_bsum[b]);
        if (t < CHUNK && base + t < N) {
            int o = g_off[base + t] + boff;
            g_off[base + t] = o;
            g_cur[base + t] = o;
        }
    }
    gbar(4);

    // P5: scatter src indices into CSR order
    for (int i = gt; i < E; i += GS) {
        int dst = ei[E + i];
        int pos = atomicAdd(&g_cur[dst], 1);
        g_srcs[pos] = ei[i];
    }
    gbar(5);

    // reset barrier counters for the next graph replay
    if (b == 0 && t < 8) g_c[t] = 0;
}

// ---------------- GEMM: C[M,128] = A[M,128] @ B[128,128], f32x2 ----------------
template<bool EPILOG>
__global__ void __launch_bounds__(256) gemm128x2(
    const float* __restrict__ A, const float* __restrict__ B,
    const float* __restrict__ bias, float* __restrict__ C, int M)
{
    __shared__ __align__(16) float Xs[32][66];    // [k][row]
    __shared__ __align__(16) float Wd[32][256];   // [k][2c+{0,1}] duplicated B

    const int tid = threadIdx.x;
    const int tx = tid & 31;
    const int ty = tid >> 5;
    const int row0 = blockIdx.x * 64;

    unsigned long long acc[4][4];
#pragma unroll
    for (int p = 0; p < 4; ++p)
#pragma unroll
        for (int q = 0; q < 4; ++q) acc[p][q] = 0ull;

#pragma unroll
    for (int kc = 0; kc < 4; ++kc) {
#pragma unroll
        for (int u = 0; u < 2; ++u) {
            int f = tid + u * 256;
            int r = f >> 3, c4 = f & 7;
            int row = row0 + r;
            float4 v = make_float4(0.f, 0.f, 0.f, 0.f);
            if (row < M)
                v = *reinterpret_cast<const float4*>(&A[(size_t)row * CH + kc * 32 + c4 * 4]);
            Xs[c4 * 4 + 0][r] = v.x;
            Xs[c4 * 4 + 1][r] = v.y;
            Xs[c4 * 4 + 2][r] = v.z;
            Xs[c4 * 4 + 3][r] = v.w;
        }
#pragma unroll
        for (int u = 0; u < 4; ++u) {
            int f = tid + u * 256;
            int r = f >> 5, c4 = f & 31;
            float4 v = *reinterpret_cast<const float4*>(&B[(size_t)(kc * 32 + r) * CH + c4 * 4]);
            float4 d0 = make_float4(v.x, v.x, v.y, v.y);
            float4 d1 = make_float4(v.z, v.z, v.w, v.w);
            *reinterpret_cast<float4*>(&Wd[r][c4 * 8])     = d0;
            *reinterpret_cast<float4*>(&Wd[r][c4 * 8 + 4]) = d1;
        }
        __syncthreads();

#pragma unroll
        for (int k = 0; k < 32; ++k) {
            unsigned long long a[4], b[4];
#pragma unroll
            for (int p = 0; p < 4; ++p)
                a[p] = *reinterpret_cast<const unsigned long long*>(&Xs[k][ty * 8 + 2 * p]);
#pragma unroll
            for (int q = 0; q < 4; ++q)
                b[q] = *reinterpret_cast<const unsigned long long*>(&Wd[k][2 * tx + 64 * q]);
#pragma unroll
            for (int p = 0; p < 4; ++p)
#pragma unroll
                for (int q = 0; q < 4; ++q)
                    fma2(acc[p][q], a[p], b[q]);
        }
        __syncthreads();
    }

    float bv[4];
    if (EPILOG) {
#pragma unroll
        for (int q = 0; q < 4; ++q) bv[q] = bias[tx + 32 * q];
    }

#pragma unroll
    for (int p = 0; p < 4; ++p) {
        int r0 = row0 + ty * 8 + 2 * p;
#pragma unroll
        for (int q = 0; q < 4; ++q) {
            float lo, hi;
            upk(acc[p][q], lo, hi);
            int col = tx + 32 * q;
            if (EPILOG) {
                lo = fmaxf(lo + bv[q], 0.f);
                hi = fmaxf(hi + bv[q], 0.f);
            }
            if (r0 < M)     C[(size_t)r0 * CH + col]       = lo;
            if (r0 + 1 < M) C[(size_t)(r0 + 1) * CH + col] = hi;
        }
    }
}

// ---------------- per-node attention logit components ----------------
__global__ void att_kernel(const float* __restrict__ att_s,
                           const float* __restrict__ att_d, int N)
{
    int warp = (blockIdx.x * blockDim.x + threadIdx.x) >> 5;
    if (warp >= N) return;
    int lane = threadIdx.x & 31;

    float4 hv  = *reinterpret_cast<const float4*>(&g_h[(size_t)warp * CH + lane * 4]);
    float4 asv = *reinterpret_cast<const float4*>(&att_s[lane * 4]);
    float4 adv = *reinterpret_cast<const float4*>(&att_d[lane * 4]);

    float ps = hv.x * asv.x + hv.y * asv.y + hv.z * asv.z + hv.w * asv.w;
    float pd = hv.x * adv.x + hv.y * adv.y + hv.z * adv.z + hv.w * adv.w;

    ps += __shfl_xor_sync(0xFFFFFFFFu, ps, 1);
    ps += __shfl_xor_sync(0xFFFFFFFFu, ps, 2);
    ps += __shfl_xor_sync(0xFFFFFFFFu, ps, 4);
    pd += __shfl_xor_sync(0xFFFFFFFFu, pd, 1);
    pd += __shfl_xor_sync(0xFFFFFFFFu, pd, 2);
    pd += __shfl_xor_sync(0xFFFFFFFFu, pd, 4);

    if ((lane & 7) == 0) {
        int h = lane >> 3;
        g_asrc[(size_t)warp * HEADS + h] = ps;
        g_adst[(size_t)warp * HEADS + h] = pd;
    }
}

// ---------------- gather: one warp per dst node, 4 edges in flight ----------------
__global__ void __launch_bounds__(256) gather_kernel(int N)
{
    int node = (blockIdx.x * blockDim.x + threadIdx.x) >> 5;
    if (node >= N) return;
    int lane = threadIdx.x & 31;
    int head = lane >> 3;

    int off = g_off[node];
    int deg = g_deg[node];

    float4 ad4 = *reinterpret_cast<const float4*>(&g_adst[(size_t)node * HEADS]);
    float ad_my = (lane & 16) ? ((lane & 8) ? ad4.w : ad4.z)
                              : ((lane & 8) ? ad4.y : ad4.x);

    float a0 = 0.f, a1 = 0.f, a2 = 0.f, a3 = 0.f;
    float s_my = 0.f;

    for (int base = 0; base < deg; base += 32) {
        int idx = 0;
        if (base + lane < deg) idx = g_srcs[off + base + lane];
        int cnt = min(32, deg - base);
        int j = 0;
        for (; j + 4 <= cnt; j += 4) {
            int s0 = __shfl_sync(0xFFFFFFFFu, idx, j);
            int s1 = __shfl_sync(0xFFFFFFFFu, idx, j + 1);
            int s2 = __shfl_sync(0xFFFFFFFFu, idx, j + 2);
            int s3 = __shfl_sync(0xFFFFFFFFu, idx, j + 3);
            // issue all loads before any consumer (MLP = 4 per lane)
            float as0 = __ldg(&g_asrc[(size_t)s0 * HEADS + head]);
            float as1 = __ldg(&g_asrc[(size_t)s1 * HEADS + head]);
            float as2 = __ldg(&g_asrc[(size_t)s2 * HEADS + head]);
            float as3 = __ldg(&g_asrc[(size_t)s3 * HEADS + head]);
            float4 h0 = *reinterpret_cast<const float4*>(&g_h[(size_t)s0 * CH + lane * 4]);
            float4 h1 = *reinterpret_cast<const float4*>(&g_h[(size_t)s1 * CH + lane * 4]);
            float4 h2 = *reinterpret_cast<const float4*>(&g_h[(size_t)s2 * CH + lane * 4]);
            float4 h3 = *reinterpret_cast<const float4*>(&g_h[(size_t)s3 * CH + lane * 4]);

            float e0 = as0 + ad_my; e0 = (e0 > 0.f) ? e0 : NEG_SLOPE * e0;
            float e1 = as1 + ad_my; e1 = (e1 > 0.f) ? e1 : NEG_SLOPE * e1;
            float e2 = as2 + ad_my; e2 = (e2 > 0.f) ? e2 : NEG_SLOPE * e2;
            float e3 = as3 + ad_my; e3 = (e3 > 0.f) ? e3 : NEG_SLOPE * e3;
            float x0 = __expf(e0), x1 = __expf(e1), x2 = __expf(e2), x3 = __expf(e3);

            a0 = fmaf(x0, h0.x, a0); a1 = fmaf(x0, h0.y, a1);
            a2 = fmaf(x0, h0.z, a2); a3 = fmaf(x0, h0.w, a3);
            a0 = fmaf(x1, h1.x, a0); a1 = fmaf(x1, h1.y, a1);
            a2 = fmaf(x1, h1.z, a2); a3 = fmaf(x1, h1.w, a3);
            a0 = fmaf(x2, h2.x, a0); a1 = fmaf(x2, h2.y, a1);
            a2 = fmaf(x2, h2.z, a2); a3 = fmaf(x2, h2.w, a3);
            a0 = fmaf(x3, h3.x, a0); a1 = fmaf(x3, h3.y, a1);
            a2 = fmaf(x3, h3.z, a2); a3 = fmaf(x3, h3.w, a3);
            s_my += x0 + x1 + x2 + x3;
        }
        for (; j < cnt; ++j) {
            int src = __shfl_sync(0xFFFFFFFFu, idx, j);
            float as_my = __ldg(&g_asrc[(size_t)src * HEADS + head]);
            float eh = as_my + ad_my;
            eh = (eh > 0.f) ? eh : NEG_SLOPE * eh;
            float ex = __expf(eh);
            float4 hv = *reinterpret_cast<const float4*>(&g_h[(size_t)src * CH + lane * 4]);
            a0 = fmaf(ex, hv.x, a0);
            a1 = fmaf(ex, hv.y, a1);
            a2 = fmaf(ex, hv.z, a2);
            a3 = fmaf(ex, hv.w, a3);
            s_my += ex;
        }
    }

    float inv = 1.f / (s_my + 1e-16f);
    float4 o = make_float4(a0 * inv, a1 * inv, a2 * inv, a3 * inv);
    *reinterpret_cast<float4*>(&g_accum[(size_t)node * CH + lane * 4]) = o;
}

// ---------------- launch ----------------
extern "C" void kernel_launch(void* const* d_in, const int* in_sizes, int n_in,
                              void* d_out, int out_size)
{
    const float* x     = (const float*)d_in[0];
    const int*   ei    = (const int*)  d_in[1];
    const float* W     = (const float*)d_in[2];
    const float* att_s = (const float*)d_in[3];
    const float* att_d = (const float*)d_in[4];
    const float* lin_w = (const float*)d_in[5];
    const float* lin_b = (const float*)d_in[6];
    float* out = (float*)d_out;

    int N = in_sizes[0] / CH;    // 100000
    int E = in_sizes[1] / 2;     // 1600000

    void *p_h, *p_acc;
    cudaGetSymbolAddress(&p_h, g_h);
    cudaGetSymbolAddress(&p_acc, g_accum);

    int gemm_blocks = (N + 63) / 64;

    csr_build<<<NBLK, CBS>>>(ei, E, N);                           // 0
    gemm128x2<false><<<gemm_blocks, 256>>>(x, W, nullptr, (float*)p_h, N);   // 1
    att_kernel<<<(N * 32 + 255) / 256, 256>>>(att_s, att_d, N);   // 2
    gather_kernel<<<(N * 32 + 255) / 256, 256>>>(N);              // 3  <- profiled
    gemm128x2<true><<<gemm_blocks, 256>>>((const float*)p_acc, lin_w, lin_b, out, N);  // 4
}

// round 5
// speedup vs baseline: 2.0802x; 1.5233x over previous
#include <cuda_runtime.h>
#include <cuda_bf16.h>
#include <cstdint>

#define N_NODES 100000
#define N_EDGES 1600000
#define CH 128          // IN_CH = HEADS*HID = OUT_CH = 128
#define HEADS 4
#define HID 32
#define NEG_SLOPE 0.2f
#define NBLK 148
#define CBS 1024

// ---------------- scratch (static device globals; no allocation) ----------------
__device__ float g_h[(size_t)N_NODES * CH];       // x @ W                  (51.2 MB)
__device__ float g_accum[(size_t)N_NODES * CH];   // normalized messages    (51.2 MB)
__device__ float g_asrc[(size_t)N_NODES * HEADS];
__device__ float g_adst[(size_t)N_NODES * HEADS];
__device__ int   g_deg[N_NODES];
__device__ int   g_off[N_NODES];
__device__ int   g_cur[N_NODES];
__device__ int   g_srcs[N_EDGES];
__device__ int   g_bsum[NBLK];
__device__ unsigned g_c[8];                        // grid-barrier counters (zero-init)
// pre-swizzled bf16 hi/lo images of W^T and lin_w^T ([n][k] layout, 32KB each)
__device__ __align__(16) unsigned char g_whi[32768];
__device__ __align__(16) unsigned char g_wlo[32768];
__device__ __align__(16) unsigned char g_lwhi[32768];
__device__ __align__(16) unsigned char g_lwlo[32768];

// ---------------- helpers ----------------
__device__ __forceinline__ uint32_t s2u(const void* p) {
    uint32_t a;
    asm("{ .reg .u64 t; cvta.to.shared.u64 t, %1; cvt.u32.u64 %0, t; }" : "=r"(a) : "l"(p));
    return a;
}

// swizzled byte offset inside a [rows][128 bf16] tile (256B rows, XOR-16B-chunk swizzle)
__device__ __forceinline__ uint32_t swz(int row, int col) {
    return (uint32_t)(row * 256 + ((((col >> 3) ^ (row & 7))) << 4) + (col & 7) * 2);
}

#define LDSM4(r, addr) \
    asm volatile("ldmatrix.sync.aligned.m8n8.x4.shared.b16 {%0,%1,%2,%3}, [%4];" \
        : "=r"((r)[0]), "=r"((r)[1]), "=r"((r)[2]), "=r"((r)[3]) : "r"(addr))

#define MMA16816(d, a, b0, b1) \
    asm volatile("mma.sync.aligned.m16n8k16.row.col.f32.bf16.bf16.f32 " \
        "{%0,%1,%2,%3}, {%4,%5,%6,%7}, {%8,%9}, {%0,%1,%2,%3};" \
        : "+f"((d)[0]), "+f"((d)[1]), "+f"((d)[2]), "+f"((d)[3]) \
        : "r"((a)[0]), "r"((a)[1]), "r"((a)[2]), "r"((a)[3]), "r"(b0), "r"(b1))

// ---------------- software grid barrier (co-resident grid of NBLK blocks) ----------------
__device__ __forceinline__ void gbar(int ph) {
    __syncthreads();
    if (threadIdx.x == 0) {
        __threadfence();
        atomicAdd(&g_c[ph], 1u);
        while (*(volatile unsigned*)&g_c[ph] < (unsigned)NBLK) { }
        __threadfence();
    }
    __syncthreads();
}

// ---------------- fused CSR build ----------------
__global__ void __launch_bounds__(CBS, 1) csr_build(const int* __restrict__ ei, int E, int N)
{
    __shared__ int sm[CBS];
    const int b = blockIdx.x, t = threadIdx.x;
    const int gt = b * CBS + t;
    const int GS = NBLK * CBS;
    const int CHUNK = (N + NBLK - 1) / NBLK;
    const int base = b * CHUNK;

    for (int i = gt; i < N; i += GS) g_deg[i] = 0;
    gbar(0);

    for (int i = gt; i < E; i += GS) atomicAdd(&g_deg[ei[E + i]], 1);
    gbar(1);

    int myv = 0;
    if (t < CHUNK && base + t < N) myv = __ldcg(&g_deg[base + t]);
    sm[t] = myv;
    __syncthreads();
#pragma unroll
    for (int d = 1; d < CBS; d <<= 1) {
        int v2 = (t >= d) ? sm[t - d] : 0;
        __syncthreads();
        sm[t] += v2;
        __syncthreads();
    }
    int incl = sm[t];
    if (t < CHUNK && base + t < N) g_off[base + t] = incl - myv;
    if (t == CBS - 1) g_bsum[b] = incl;
    gbar(2);

    if (b == 0) {
        int v = (t < NBLK) ? __ldcg(&g_bsum[t]) : 0;
        sm[t] = v;
        __syncthreads();
#pragma unroll
        for (int d = 1; d < CBS; d <<= 1) {
            int v2 = (t >= d) ? sm[t - d] : 0;
            __syncthreads();
            sm[t] += v2;
            __syncthreads();
        }
        if (t < NBLK) g_bsum[t] = sm[t] - v;
    }
    gbar(3);

    {
        int boff = __ldcg(&g_bsum[b]);
        if (t < CHUNK && base + t < N) {
            int o = g_off[base + t] + boff;
            g_off[base + t] = o;
            g_cur[base + t] = o;
        }
    }
    gbar(4);

    for (int i = gt; i < E; i += GS) {
        int dst = ei[E + i];
        int pos = atomicAdd(&g_cur[dst], 1);
        g_srcs[pos] = ei[i];
    }
    gbar(5);

    if (b == 0 && t < 8) g_c[t] = 0;
}

// ---------------- prep: B^T (=W[k][n] -> [n][k]) split to bf16 hi/lo, swizzled ----------------
__global__ void prep_w(const float* __restrict__ src,
                       unsigned char* __restrict__ dhi, unsigned char* __restrict__ dlo)
{
    int idx = blockIdx.x * blockDim.x + threadIdx.x;   // 16384
    int n = idx >> 7, k = idx & 127;
    float v = src[k * CH + n];
    __nv_bfloat16 h = __float2bfloat16(v);
    __nv_bfloat16 l = __float2bfloat16(v - __bfloat162float(h));
    uint32_t o = swz(n, k);
    *reinterpret_cast<__nv_bfloat16*>(dhi + o) = h;
    *reinterpret_cast<__nv_bfloat16*>(dlo + o) = l;
}

// ---------------- tensor-core GEMM: C[M,128] = A[M,128] @ B, split-bf16 3-product ----------------
// block: 256 thr, 64-row tile; warp w: rows 16*(w>>1), cols 64*(w&1)
template<bool EPILOG>
__global__ void __launch_bounds__(256, 2) gemm_mma(
    const float* __restrict__ A,
    const unsigned char* __restrict__ Bhi_g, const unsigned char* __restrict__ Blo_g,
    const float* __restrict__ bias, float* __restrict__ C, int M)
{
    extern __shared__ __align__(16) unsigned char smem[];
    // layout: A_hi 16K | A_lo 16K | B_hi 32K | B_lo 32K
    const uint32_t sb = s2u(smem);
    const int tid = threadIdx.x, lane = tid & 31, w = tid >> 5;
    const int row0 = blockIdx.x * 64;

    // copy pre-swizzled B tiles
    {
        const int4* bh = reinterpret_cast<const int4*>(Bhi_g);
        const int4* bl = reinterpret_cast<const int4*>(Blo_g);
        int4* dh = reinterpret_cast<int4*>(smem + 32768);
        int4* dl = reinterpret_cast<int4*>(smem + 65536);
#pragma unroll
        for (int u = 0; u < 8; ++u) {
            int f = tid + u * 256;
            dh[f] = bh[f];
            dl[f] = bl[f];
        }
    }

    // stage A tile: fp32 -> bf16 hi/lo, swizzled
#pragma unroll
    for (int u = 0; u < 8; ++u) {
        int f = tid + u * 256;              // 2048 float4
        int r = f >> 5;                     // 0..63
        int c = (f & 31) * 4;
        float4 v = make_float4(0.f, 0.f, 0.f, 0.f);
        if (row0 + r < M)
            v = *reinterpret_cast<const float4*>(&A[(size_t)(row0 + r) * CH + c]);
        __nv_bfloat162 h01 = __floats2bfloat162_rn(v.x, v.y);
        __nv_bfloat162 h23 = __floats2bfloat162_rn(v.z, v.w);
        float l0 = v.x - __bfloat162float(h01.x);
        float l1 = v.y - __bfloat162float(h01.y);
        float l2 = v.z - __bfloat162float(h23.x);
        float l3 = v.w - __bfloat162float(h23.y);
        __nv_bfloat162 lo01 = __floats2bfloat162_rn(l0, l1);
        __nv_bfloat162 lo23 = __floats2bfloat162_rn(l2, l3);
        uint32_t o = swz(r, c);
        uint2 uh, ul;
        uh.x = *reinterpret_cast<uint32_t*>(&h01);
        uh.y = *reinterpret_cast<uint32_t*>(&h23);
        ul.x = *reinterpret_cast<uint32_t*>(&lo01);
        ul.y = *reinterpret_cast<uint32_t*>(&lo23);
        *reinterpret_cast<uint2*>(smem + o)         = uh;
        *reinterpret_cast<uint2*>(smem + 16384 + o) = ul;
    }
    __syncthreads();

    const int wr = (w >> 1) * 16;          // warp row offset in tile
    const int wc = (w & 1) * 64;           // warp col offset

    float acc[8][4];
#pragma unroll
    for (int j = 0; j < 8; ++j)
#pragma unroll
        for (int q = 0; q < 4; ++q) acc[j][q] = 0.f;

    // lane address components (ldmatrix fragment conventions)
    const int arow  = wr + (lane & 7) + ((lane >> 3) & 1) * 8;
    const int asel  = lane >> 4;           // k8 selector for A
    const int arow7 = arow & 7;
    const int bg_row = (lane & 7) + ((lane >> 4) & 1) * 8;
    const int bsel   = (lane >> 3) & 1;    // k8 selector for B

#pragma unroll
    for (int kk = 0; kk < 8; ++kk) {
        uint32_t a_hi[4], a_lo[4];
        uint32_t aaddr = sb + (uint32_t)(arow * 256) +
                         (uint32_t)((((kk * 2 + asel) ^ arow7)) << 4);
        LDSM4(a_hi, aaddr);
        LDSM4(a_lo, aaddr + 16384);

        uint32_t b_hi[16], b_lo[16];
#pragma unroll
        for (int g = 0; g < 4; ++g) {
            int brow = wc + g * 16 + bg_row;
            uint32_t baddr = sb + 32768 + (uint32_t)(brow * 256) +
                             (uint32_t)((((kk * 2 + bsel) ^ (brow & 7))) << 4);
            LDSM4(&b_hi[g * 4], baddr);
            LDSM4(&b_lo[g * 4], baddr + 32768);
        }

#pragma unroll
        for (int j = 0; j < 8; ++j) {
            int i0 = (j >> 1) * 4 + (j & 1) * 2;
            MMA16816(acc[j], a_hi, b_hi[i0], b_hi[i0 + 1]);
            MMA16816(acc[j], a_hi, b_lo[i0], b_lo[i0 + 1]);
            MMA16816(acc[j], a_lo, b_hi[i0], b_hi[i0 + 1]);
        }
    }

    // epilogue: D frag: d0,d1 -> (row lane/4, cols 2(lane%4)+{0,1}); d2,d3 -> row+8
    const int r_g = row0 + wr + (lane >> 2);
#pragma unroll
    for (int j = 0; j < 8; ++j) {
        int n0 = wc + j * 8 + (lane & 3) * 2;
        float2 v0 = make_float2(acc[j][0], acc[j][1]);
        float2 v1 = make_float2(acc[j][2], acc[j][3]);
        if (EPILOG) {
            float b0 = __ldg(&bias[n0]), b1 = __ldg(&bias[n0 + 1]);
            v0.x = fmaxf(v0.x + b0, 0.f); v0.y = fmaxf(v0.y + b1, 0.f);
            v1.x = fmaxf(v1.x + b0, 0.f); v1.y = fmaxf(v1.y + b1, 0.f);
        }
        if (r_g < M)
            *reinterpret_cast<float2*>(&C[(size_t)r_g * CH + n0]) = v0;
        if (r_g + 8 < M)
            *reinterpret_cast<float2*>(&C[(size_t)(r_g + 8) * CH + n0]) = v1;
    }
}

// ---------------- per-node attention logit components ----------------
__global__ void att_kernel(const float* __restrict__ att_s,
                           const float* __restrict__ att_d, int N)
{
    int warp = (blockIdx.x * blockDim.x + threadIdx.x) >> 5;
    if (warp >= N) return;
    int lane = threadIdx.x & 31;

    float4 hv  = *reinterpret_cast<const float4*>(&g_h[(size_t)warp * CH + lane * 4]);
    float4 asv = *reinterpret_cast<const float4*>(&att_s[lane * 4]);
    float4 adv = *reinterpret_cast<const float4*>(&att_d[lane * 4]);

    float ps = hv.x * asv.x + hv.y * asv.y + hv.z * asv.z + hv.w * asv.w;
    float pd = hv.x * adv.x + hv.y * adv.y + hv.z * adv.z + hv.w * adv.w;

    ps += __shfl_xor_sync(0xFFFFFFFFu, ps, 1);
    ps += __shfl_xor_sync(0xFFFFFFFFu, ps, 2);
    ps += __shfl_xor_sync(0xFFFFFFFFu, ps, 4);
    pd += __shfl_xor_sync(0xFFFFFFFFu, pd, 1);
    pd += __shfl_xor_sync(0xFFFFFFFFu, pd, 2);
    pd += __shfl_xor_sync(0xFFFFFFFFu, pd, 4);

    if ((lane & 7) == 0) {
        int h = lane >> 3;
        g_asrc[(size_t)warp * HEADS + h] = ps;
        g_adst[(size_t)warp * HEADS + h] = pd;
    }
}

// ---------------- gather: one warp per dst node, 4 edges in flight ----------------
__global__ void __launch_bounds__(256) gather_kernel(int N)
{
    int node = (blockIdx.x * blockDim.x + threadIdx.x) >> 5;
    if (node >= N) return;
    int lane = threadIdx.x & 31;
    int head = lane >> 3;

    int off = g_off[node];
    int deg = g_deg[node];

    float4 ad4 = *reinterpret_cast<const float4*>(&g_adst[(size_t)node * HEADS]);
    float ad_my = (lane & 16) ? ((lane & 8) ? ad4.w : ad4.z)
                              : ((lane & 8) ? ad4.y : ad4.x);

    float a0 = 0.f, a1 = 0.f, a2 = 0.f, a3 = 0.f;
    float s_my = 0.f;

    for (int base = 0; base < deg; base += 32) {
        int idx = 0;
        if (base + lane < deg) idx = g_srcs[off + base + lane];
        int cnt = min(32, deg - base);
        int j = 0;
        for (; j + 4 <= cnt; j += 4) {
            int s0 = __shfl_sync(0xFFFFFFFFu, idx, j);
            int s1 = __shfl_sync(0xFFFFFFFFu, idx, j + 1);
            int s2 = __shfl_sync(0xFFFFFFFFu, idx, j + 2);
            int s3 = __shfl_sync(0xFFFFFFFFu, idx, j + 3);
            float as0 = __ldg(&g_asrc[(size_t)s0 * HEADS + head]);
            float as1 = __ldg(&g_asrc[(size_t)s1 * HEADS + head]);
            float as2 = __ldg(&g_asrc[(size_t)s2 * HEADS + head]);
            float as3 = __ldg(&g_asrc[(size_t)s3 * HEADS + head]);
            float4 h0 = *reinterpret_cast<const float4*>(&g_h[(size_t)s0 * CH + lane * 4]);
            float4 h1 = *reinterpret_cast<const float4*>(&g_h[(size_t)s1 * CH + lane * 4]);
            float4 h2 = *reinterpret_cast<const float4*>(&g_h[(size_t)s2 * CH + lane * 4]);
            float4 h3 = *reinterpret_cast<const float4*>(&g_h[(size_t)s3 * CH + lane * 4]);

            float e0 = as0 + ad_my; e0 = (e0 > 0.f) ? e0 : NEG_SLOPE * e0;
            float e1 = as1 + ad_my; e1 = (e1 > 0.f) ? e1 : NEG_SLOPE * e1;
            float e2 = as2 + ad_my; e2 = (e2 > 0.f) ? e2 : NEG_SLOPE * e2;
            float e3 = as3 + ad_my; e3 = (e3 > 0.f) ? e3 : NEG_SLOPE * e3;
            float x0 = __expf(e0), x1 = __expf(e1), x2 = __expf(e2), x3 = __expf(e3);

            a0 = fmaf(x0, h0.x, a0); a1 = fmaf(x0, h0.y, a1);
            a2 = fmaf(x0, h0.z, a2); a3 = fmaf(x0, h0.w, a3);
            a0 = fmaf(x1, h1.x, a0); a1 = fmaf(x1, h1.y, a1);
            a2 = fmaf(x1, h1.z, a2); a3 = fmaf(x1, h1.w, a3);
            a0 = fmaf(x2, h2.x, a0); a1 = fmaf(x2, h2.y, a1);
            a2 = fmaf(x2, h2.z, a2); a3 = fmaf(x2, h2.w, a3);
            a0 = fmaf(x3, h3.x, a0); a1 = fmaf(x3, h3.y, a1);
            a2 = fmaf(x3, h3.z, a2); a3 = fmaf(x3, h3.w, a3);
            s_my += x0 + x1 + x2 + x3;
        }
        for (; j < cnt; ++j) {
            int src = __shfl_sync(0xFFFFFFFFu, idx, j);
            float as_my = __ldg(&g_asrc[(size_t)src * HEADS + head]);
            float eh = as_my + ad_my;
            eh = (eh > 0.f) ? eh : NEG_SLOPE * eh;
            float ex = __expf(eh);
            float4 hv = *reinterpret_cast<const float4*>(&g_h[(size_t)src * CH + lane * 4]);
            a0 = fmaf(ex, hv.x, a0);
            a1 = fmaf(ex, hv.y, a1);
            a2 = fmaf(ex, hv.z, a2);
            a3 = fmaf(ex, hv.w, a3);
            s_my += ex;
        }
    }

    float inv = 1.f / (s_my + 1e-16f);
    float4 o = make_float4(a0 * inv, a1 * inv, a2 * inv, a3 * inv);
    *reinterpret_cast<float4*>(&g_accum[(size_t)node * CH + lane * 4]) = o;
}

// ---------------- launch ----------------
extern "C" void kernel_launch(void* const* d_in, const int* in_sizes, int n_in,
                              void* d_out, int out_size)
{
    const float* x     = (const float*)d_in[0];
    const int*   ei    = (const int*)  d_in[1];
    const float* W     = (const float*)d_in[2];
    const float* att_s = (const float*)d_in[3];
    const float* att_d = (const float*)d_in[4];
    const float* lin_w = (const float*)d_in[5];
    const float* lin_b = (const float*)d_in[6];
    float* out = (float*)d_out;

    int N = in_sizes[0] / CH;    // 100000
    int E = in_sizes[1] / 2;     // 1600000

    void *p_h, *p_acc, *p_whi, *p_wlo, *p_lwhi, *p_lwlo;
    cudaGetSymbolAddress(&p_h, g_h);
    cudaGetSymbolAddress(&p_acc, g_accum);
    cudaGetSymbolAddress(&p_whi, g_whi);
    cudaGetSymbolAddress(&p_wlo, g_wlo);
    cudaGetSymbolAddress(&p_lwhi, g_lwhi);
    cudaGetSymbolAddress(&p_lwlo, g_lwlo);

    const int SMEM = 98304;
    cudaFuncSetAttribute(gemm_mma<false>, cudaFuncAttributeMaxDynamicSharedMemorySize, SMEM);
    cudaFuncSetAttribute(gemm_mma<true>,  cudaFuncAttributeMaxDynamicSharedMemorySize, SMEM);

    int gemm_blocks = (N + 63) / 64;

    csr_build<<<NBLK, CBS>>>(ei, E, N);                                       // 0
    prep_w<<<64, 256>>>(W, (unsigned char*)p_whi, (unsigned char*)p_wlo);     // 1
    prep_w<<<64, 256>>>(lin_w, (unsigned char*)p_lwhi, (unsigned char*)p_lwlo); // 2
    gemm_mma<false><<<gemm_blocks, 256, SMEM>>>(                              // 3 <- profiled
        x, (const unsigned char*)p_whi, (const unsigned char*)p_wlo,
        nullptr, (float*)p_h, N);
    att_kernel<<<(N * 32 + 255) / 256, 256>>>(att_s, att_d, N);               // 4
    gather_kernel<<<(N * 32 + 255) / 256, 256>>>(N);                          // 5
    gemm_mma<true><<<gemm_blocks, 256, SMEM>>>(                               // 6
        (const float*)p_acc, (const unsigned char*)p_lwhi, (const unsigned char*)p_lwlo,
        lin_b, out, N);
}

// round 6
// speedup vs baseline: 2.1461x; 1.0317x over previous
#include <cuda_runtime.h>
#include <cuda_bf16.h>
#include <cstdint>

#define N_NODES 100000
#define N_EDGES 1600000
#define CH 128          // IN_CH = HEADS*HID = OUT_CH = 128
#define HEADS 4
#define HID 32
#define NEG_SLOPE 0.2f
#define NBLK 148
#define CBS 1024

// ---------------- scratch (static device globals; no allocation) ----------------
__device__ float g_h[(size_t)N_NODES * CH];       // x @ W                  (51.2 MB)
__device__ float g_accum[(size_t)N_NODES * CH];   // normalized messages    (51.2 MB)
__device__ float g_asrc[(size_t)N_NODES * HEADS];
__device__ float g_adst[(size_t)N_NODES * HEADS];
__device__ int   g_deg[N_NODES];
__device__ int   g_off[N_NODES];
__device__ int   g_cur[N_NODES];
__device__ int   g_srcs[N_EDGES];
__device__ int   g_bsum[NBLK];
__device__ unsigned g_c[8];                        // grid-barrier counters (zero-init)
// pre-swizzled bf16 hi/lo images of W^T and lin_w^T ([n][k] layout, 32KB each)
__device__ __align__(16) unsigned char g_whi[32768];
__device__ __align__(16) unsigned char g_wlo[32768];
__device__ __align__(16) unsigned char g_lwhi[32768];
__device__ __align__(16) unsigned char g_lwlo[32768];

// ---------------- helpers ----------------
__device__ __forceinline__ uint32_t s2u(const void* p) {
    uint32_t a;
    asm("{ .reg .u64 t; cvta.to.shared.u64 t, %1; cvt.u32.u64 %0, t; }" : "=r"(a) : "l"(p));
    return a;
}

// swizzled byte offset inside a [rows][128 bf16] tile (256B rows, XOR-16B-chunk swizzle)
__device__ __forceinline__ uint32_t swz(int row, int col) {
    return (uint32_t)(row * 256 + ((((col >> 3) ^ (row & 7))) << 4) + (col & 7) * 2);
}

#define LDSM4(r, addr) \
    asm volatile("ldmatrix.sync.aligned.m8n8.x4.shared.b16 {%0,%1,%2,%3}, [%4];" \
        : "=r"((r)[0]), "=r"((r)[1]), "=r"((r)[2]), "=r"((r)[3]) : "r"(addr))

#define MMA16816(d, a, b0, b1) \
    asm volatile("mma.sync.aligned.m16n8k16.row.col.f32.bf16.bf16.f32 " \
        "{%0,%1,%2,%3}, {%4,%5,%6,%7}, {%8,%9}, {%0,%1,%2,%3};" \
        : "+f"((d)[0]), "+f"((d)[1]), "+f"((d)[2]), "+f"((d)[3]) \
        : "r"((a)[0]), "r"((a)[1]), "r"((a)[2]), "r"((a)[3]), "r"(b0), "r"(b1))

// ---------------- software grid barrier (co-resident grid of NBLK blocks) ----------------
__device__ __forceinline__ void gbar(int ph) {
    __syncthreads();
    if (threadIdx.x == 0) {
        __threadfence();
        atomicAdd(&g_c[ph], 1u);
        while (*(volatile unsigned*)&g_c[ph] < (unsigned)NBLK) { __nanosleep(64); }
        __threadfence();
    }
    __syncthreads();
}

// ---------------- fused CSR build ----------------
__global__ void __launch_bounds__(CBS, 1) csr_build(const int* __restrict__ ei, int E, int N)
{
    __shared__ int sm[CBS];
    const int b = blockIdx.x, t = threadIdx.x;
    const int gt = b * CBS + t;
    const int GS = NBLK * CBS;
    const int CHUNK = (N + NBLK - 1) / NBLK;
    const int base = b * CHUNK;

    for (int i = gt; i < N; i += GS) g_deg[i] = 0;
    gbar(0);

    for (int i = gt; i < E; i += GS) atomicAdd(&g_deg[ei[E + i]], 1);
    gbar(1);

    int myv = 0;
    if (t < CHUNK && base + t < N) myv = __ldcg(&g_deg[base + t]);
    sm[t] = myv;
    __syncthreads();
#pragma unroll
    for (int d = 1; d < CBS; d <<= 1) {
        int v2 = (t >= d) ? sm[t - d] : 0;
        __syncthreads();
        sm[t] += v2;
        __syncthreads();
    }
    int incl = sm[t];
    if (t < CHUNK && base + t < N) g_off[base + t] = incl - myv;
    if (t == CBS - 1) g_bsum[b] = incl;
    gbar(2);

    if (b == 0) {
        int v = (t < NBLK) ? __ldcg(&g_bsum[t]) : 0;
        sm[t] = v;
        __syncthreads();
#pragma unroll
        for (int d = 1; d < CBS; d <<= 1) {
            int v2 = (t >= d) ? sm[t - d] : 0;
            __syncthreads();
            sm[t] += v2;
            __syncthreads();
        }
        if (t < NBLK) g_bsum[t] = sm[t] - v;
    }
    gbar(3);

    {
        int boff = __ldcg(&g_bsum[b]);
        if (t < CHUNK && base + t < N) {
            int o = g_off[base + t] + boff;
            g_off[base + t] = o;
            g_cur[base + t] = o;
        }
    }
    gbar(4);

    for (int i = gt; i < E; i += GS) {
        int dst = ei[E + i];
        int pos = atomicAdd(&g_cur[dst], 1);
        g_srcs[pos] = ei[i];
    }
    gbar(5);

    if (b == 0 && t < 8) g_c[t] = 0;
}

// ---------------- prep: B^T (=W[k][n] -> [n][k]) split to bf16 hi/lo, swizzled ----------------
__global__ void prep_w(const float* __restrict__ src,
                       unsigned char* __restrict__ dhi, unsigned char* __restrict__ dlo)
{
    int idx = blockIdx.x * blockDim.x + threadIdx.x;   // 16384
    int n = idx >> 7, k = idx & 127;
    float v = src[k * CH + n];
    __nv_bfloat16 h = __float2bfloat16(v);
    __nv_bfloat16 l = __float2bfloat16(v - __bfloat162float(h));
    uint32_t o = swz(n, k);
    *reinterpret_cast<__nv_bfloat16*>(dhi + o) = h;
    *reinterpret_cast<__nv_bfloat16*>(dlo + o) = l;
}

// ---------------- tensor-core GEMM: C[M,128] = A[M,128] @ B, split-bf16 3-product ----------------
// MODE 0: gemm1 -> C=g_h, fused a_src/a_dst epilogue (v0=att_s, v1=att_d)
// MODE 1: gemm2 -> C=out with bias(v0) + ReLU
template<int MODE>
__global__ void __launch_bounds__(256, 1) gemm_mma(
    const float* __restrict__ A,
    const unsigned char* __restrict__ Bhi_g, const unsigned char* __restrict__ Blo_g,
    const float* __restrict__ v0, const float* __restrict__ v1,
    float* __restrict__ C, int M)
{
    extern __shared__ __align__(16) unsigned char smem[];
    // layout: A_hi 16K | A_lo 16K | B_hi 32K | B_lo 32K
    const uint32_t sb = s2u(smem);
    const int tid = threadIdx.x, lane = tid & 31, w = tid >> 5;
    const int row0 = blockIdx.x * 64;

    // copy pre-swizzled B tiles
    {
        const int4* bh = reinterpret_cast<const int4*>(Bhi_g);
        const int4* bl = reinterpret_cast<const int4*>(Blo_g);
        int4* dh = reinterpret_cast<int4*>(smem + 32768);
        int4* dl = reinterpret_cast<int4*>(smem + 65536);
#pragma unroll
        for (int u = 0; u < 8; ++u) {
            int f = tid + u * 256;
            dh[f] = bh[f];
            dl[f] = bl[f];
        }
    }

    // stage A tile: fp32 -> bf16 hi/lo, swizzled
#pragma unroll
    for (int u = 0; u < 8; ++u) {
        int f = tid + u * 256;              // 2048 float4
        int r = f >> 5;                     // 0..63
        int c = (f & 31) * 4;
        float4 v = make_float4(0.f, 0.f, 0.f, 0.f);
        if (row0 + r < M)
            v = *reinterpret_cast<const float4*>(&A[(size_t)(row0 + r) * CH + c]);
        __nv_bfloat162 h01 = __floats2bfloat162_rn(v.x, v.y);
        __nv_bfloat162 h23 = __floats2bfloat162_rn(v.z, v.w);
        float l0 = v.x - __bfloat162float(h01.x);
        float l1 = v.y - __bfloat162float(h01.y);
        float l2 = v.z - __bfloat162float(h23.x);
        float l3 = v.w - __bfloat162float(h23.y);
        __nv_bfloat162 lo01 = __floats2bfloat162_rn(l0, l1);
        __nv_bfloat162 lo23 = __floats2bfloat162_rn(l2, l3);
        uint32_t o = swz(r, c);
        uint2 uh, ul;
        uh.x = *reinterpret_cast<uint32_t*>(&h01);
        uh.y = *reinterpret_cast<uint32_t*>(&h23);
        ul.x = *reinterpret_cast<uint32_t*>(&lo01);
        ul.y = *reinterpret_cast<uint32_t*>(&lo23);
        *reinterpret_cast<uint2*>(smem + o)         = uh;
        *reinterpret_cast<uint2*>(smem + 16384 + o) = ul;
    }
    __syncthreads();

    const int wr = (w >> 1) * 16;          // warp row offset in tile
    const int wc = (w & 1) * 64;           // warp col offset

    float acc[8][4];
#pragma unroll
    for (int j = 0; j < 8; ++j)
#pragma unroll
        for (int q = 0; q < 4; ++q) acc[j][q] = 0.f;

    const int arow  = wr + (lane & 7) + ((lane >> 3) & 1) * 8;
    const int asel  = lane >> 4;
    const int arow7 = arow & 7;
    const int bg_row = (lane & 7) + ((lane >> 4) & 1) * 8;
    const int bsel   = (lane >> 3) & 1;

#pragma unroll
    for (int kk = 0; kk < 8; ++kk) {
        uint32_t a_hi[4], a_lo[4];
        uint32_t aaddr = sb + (uint32_t)(arow * 256) +
                         (uint32_t)((((kk * 2 + asel) ^ arow7)) << 4);
        LDSM4(a_hi, aaddr);
        LDSM4(a_lo, aaddr + 16384);

        uint32_t b_hi[16], b_lo[16];
#pragma unroll
        for (int g = 0; g < 4; ++g) {
            int brow = wc + g * 16 + bg_row;
            uint32_t baddr = sb + 32768 + (uint32_t)(brow * 256) +
                             (uint32_t)((((kk * 2 + bsel) ^ (brow & 7))) << 4);
            LDSM4(&b_hi[g * 4], baddr);
            LDSM4(&b_lo[g * 4], baddr + 32768);
        }

#pragma unroll
        for (int j = 0; j < 8; ++j) {
            int i0 = (j >> 1) * 4 + (j & 1) * 2;
            MMA16816(acc[j], a_hi, b_hi[i0], b_hi[i0 + 1]);
            MMA16816(acc[j], a_hi, b_lo[i0], b_lo[i0 + 1]);
            MMA16816(acc[j], a_lo, b_hi[i0], b_hi[i0 + 1]);
        }
    }

    // epilogue: D frag rows (row0+wr+lane/4, +8), cols wc + j*8 + 2*(lane&3) + {0,1}
    const int r_g = row0 + wr + (lane >> 2);
#pragma unroll
    for (int j = 0; j < 8; ++j) {
        int n0 = wc + j * 8 + (lane & 3) * 2;
        float2 o0 = make_float2(acc[j][0], acc[j][1]);
        float2 o1 = make_float2(acc[j][2], acc[j][3]);
        if (MODE == 1) {
            float b0 = __ldg(&v0[n0]), b1 = __ldg(&v0[n0 + 1]);
            o0.x = fmaxf(o0.x + b0, 0.f); o0.y = fmaxf(o0.y + b1, 0.f);
            o1.x = fmaxf(o1.x + b0, 0.f); o1.y = fmaxf(o1.y + b1, 0.f);
        }
        if (r_g < M)
            *reinterpret_cast<float2*>(&C[(size_t)r_g * CH + n0]) = o0;
        if (r_g + 8 < M)
            *reinterpret_cast<float2*>(&C[(size_t)(r_g + 8) * CH + n0]) = o1;
    }

    if (MODE == 0) {
        // fused att projections: this warp covers 2 heads (wc/32, wc/32+1)
        float ps[2][2] = {{0.f, 0.f}, {0.f, 0.f}};   // [head-half][row-half]
        float pd[2][2] = {{0.f, 0.f}, {0.f, 0.f}};
#pragma unroll
        for (int j = 0; j < 8; ++j) {
            int n0 = wc + j * 8 + (lane & 3) * 2;
            float s0 = __ldg(&v0[n0]), s1 = __ldg(&v0[n0 + 1]);
            float d0 = __ldg(&v1[n0]), d1 = __ldg(&v1[n0 + 1]);
            int hh = j >> 2;
            ps[hh][0] += acc[j][0] * s0 + acc[j][1] * s1;
            ps[hh][1] += acc[j][2] * s0 + acc[j][3] * s1;
            pd[hh][0] += acc[j][0] * d0 + acc[j][1] * d1;
            pd[hh][1] += acc[j][2] * d0 + acc[j][3] * d1;
        }
#pragma unroll
        for (int o = 1; o < 4; o <<= 1) {
#pragma unroll
            for (int hh = 0; hh < 2; ++hh)
#pragma unroll
                for (int rh = 0; rh < 2; ++rh) {
                    ps[hh][rh] += __shfl_xor_sync(0xFFFFFFFFu, ps[hh][rh], o);
                    pd[hh][rh] += __shfl_xor_sync(0xFFFFFFFFu, pd[hh][rh], o);
                }
        }
        if ((lane & 3) == 0) {
            int h0 = wc >> 5;   // head index of first 32-col group
            if (r_g < M) {
                g_asrc[(size_t)r_g * HEADS + h0]     = ps[0][0];
                g_asrc[(size_t)r_g * HEADS + h0 + 1] = ps[1][0];
                g_adst[(size_t)r_g * HEADS + h0]     = pd[0][0];
                g_adst[(size_t)r_g * HEADS + h0 + 1] = pd[1][0];
            }
            if (r_g + 8 < M) {
                g_asrc[(size_t)(r_g + 8) * HEADS + h0]     = ps[0][1];
                g_asrc[(size_t)(r_g + 8) * HEADS + h0 + 1] = ps[1][1];
                g_adst[(size_t)(r_g + 8) * HEADS + h0]     = pd[0][1];
                g_adst[(size_t)(r_g + 8) * HEADS + h0 + 1] = pd[1][1];
            }
        }
    }
}

// ---------------- gather: one warp per dst node, 4 edges in flight ----------------
__global__ void __launch_bounds__(256) gather_kernel(int N)
{
    int node = (blockIdx.x * blockDim.x + threadIdx.x) >> 5;
    if (node >= N) return;
    int lane = threadIdx.x & 31;
    int head = lane >> 3;

    int off = g_off[node];
    int deg = g_deg[node];

    float4 ad4 = *reinterpret_cast<const float4*>(&g_adst[(size_t)node * HEADS]);
    float ad_my = (lane & 16) ? ((lane & 8) ? ad4.w : ad4.z)
                              : ((lane & 8) ? ad4.y : ad4.x);

    float a0 = 0.f, a1 = 0.f, a2 = 0.f, a3 = 0.f;
    float s_my = 0.f;

    for (int base = 0; base < deg; base += 32) {
        int idx = 0;
        if (base + lane < deg) idx = g_srcs[off + base + lane];
        int cnt = min(32, deg - base);
        int j = 0;
        for (; j + 4 <= cnt; j += 4) {
            int s0 = __shfl_sync(0xFFFFFFFFu, idx, j);
            int s1 = __shfl_sync(0xFFFFFFFFu, idx, j + 1);
            int s2 = __shfl_sync(0xFFFFFFFFu, idx, j + 2);
            int s3 = __shfl_sync(0xFFFFFFFFu, idx, j + 3);
            float as0 = __ldg(&g_asrc[(size_t)s0 * HEADS + head]);
            float as1 = __ldg(&g_asrc[(size_t)s1 * HEADS + head]);
            float as2 = __ldg(&g_asrc[(size_t)s2 * HEADS + head]);
            float as3 = __ldg(&g_asrc[(size_t)s3 * HEADS + head]);
            float4 h0 = *reinterpret_cast<const float4*>(&g_h[(size_t)s0 * CH + lane * 4]);
            float4 h1 = *reinterpret_cast<const float4*>(&g_h[(size_t)s1 * CH + lane * 4]);
            float4 h2 = *reinterpret_cast<const float4*>(&g_h[(size_t)s2 * CH + lane * 4]);
            float4 h3 = *reinterpret_cast<const float4*>(&g_h[(size_t)s3 * CH + lane * 4]);

            float e0 = as0 + ad_my; e0 = (e0 > 0.f) ? e0 : NEG_SLOPE * e0;
            float e1 = as1 + ad_my; e1 = (e1 > 0.f) ? e1 : NEG_SLOPE * e1;
            float e2 = as2 + ad_my; e2 = (e2 > 0.f) ? e2 : NEG_SLOPE * e2;
            float e3 = as3 + ad_my; e3 = (e3 > 0.f) ? e3 : NEG_SLOPE * e3;
            float x0 = __expf(e0), x1 = __expf(e1), x2 = __expf(e2), x3 = __expf(e3);

            a0 = fmaf(x0, h0.x, a0); a1 = fmaf(x0, h0.y, a1);
            a2 = fmaf(x0, h0.z, a2); a3 = fmaf(x0, h0.w, a3);
            a0 = fmaf(x1, h1.x, a0); a1 = fmaf(x1, h1.y, a1);
            a2 = fmaf(x1, h1.z, a2); a3 = fmaf(x1, h1.w, a3);
            a0 = fmaf(x2, h2.x, a0); a1 = fmaf(x2, h2.y, a1);
            a2 = fmaf(x2, h2.z, a2); a3 = fmaf(x2, h2.w, a3);
            a0 = fmaf(x3, h3.x, a0); a1 = fmaf(x3, h3.y, a1);
            a2 = fmaf(x3, h3.z, a2); a3 = fmaf(x3, h3.w, a3);
            s_my += x0 + x1 + x2 + x3;
        }
        for (; j < cnt; ++j) {
            int src = __shfl_sync(0xFFFFFFFFu, idx, j);
            float as_my = __ldg(&g_asrc[(size_t)src * HEADS + head]);
            float eh = as_my + ad_my;
            eh = (eh > 0.f) ? eh : NEG_SLOPE * eh;
            float ex = __expf(eh);
            float4 hv = *reinterpret_cast<const float4*>(&g_h[(size_t)src * CH + lane * 4]);
            a0 = fmaf(ex, hv.x, a0);
            a1 = fmaf(ex, hv.y, a1);
            a2 = fmaf(ex, hv.z, a2);
            a3 = fmaf(ex, hv.w, a3);
            s_my += ex;
        }
    }

    float inv = 1.f / (s_my + 1e-16f);
    float4 o = make_float4(a0 * inv, a1 * inv, a2 * inv, a3 * inv);
    *reinterpret_cast<float4*>(&g_accum[(size_t)node * CH + lane * 4]) = o;
}

// ---------------- launch ----------------
extern "C" void kernel_launch(void* const* d_in, const int* in_sizes, int n_in,
                              void* d_out, int out_size)
{
    const float* x     = (const float*)d_in[0];
    const int*   ei    = (const int*)  d_in[1];
    const float* W     = (const float*)d_in[2];
    const float* att_s = (const float*)d_in[3];
    const float* att_d = (const float*)d_in[4];
    const float* lin_w = (const float*)d_in[5];
    const float* lin_b = (const float*)d_in[6];
    float* out = (float*)d_out;

    int N = in_sizes[0] / CH;    // 100000
    int E = in_sizes[1] / 2;     // 1600000

    void *p_h, *p_acc, *p_whi, *p_wlo, *p_lwhi, *p_lwlo;
    cudaGetSymbolAddress(&p_h, g_h);
    cudaGetSymbolAddress(&p_acc, g_accum);
    cudaGetSymbolAddress(&p_whi, g_whi);
    cudaGetSymbolAddress(&p_wlo, g_wlo);
    cudaGetSymbolAddress(&p_lwhi, g_lwhi);
    cudaGetSymbolAddress(&p_lwlo, g_lwlo);

    const int SMEM = 98304;
    cudaFuncSetAttribute(gemm_mma<0>, cudaFuncAttributeMaxDynamicSharedMemorySize, SMEM);
    cudaFuncSetAttribute(gemm_mma<1>, cudaFuncAttributeMaxDynamicSharedMemorySize, SMEM);

    int gemm_blocks = (N + 63) / 64;

    // fork: csr_build (side stream) || prep + gemm1 (main stream)
    cudaStream_t s2;
    cudaStreamCreateWithFlags(&s2, cudaStreamNonBlocking);
    cudaEvent_t ev_fork, ev_join;
    cudaEventCreateWithFlags(&ev_fork, cudaEventDisableTiming);
    cudaEventCreateWithFlags(&ev_join, cudaEventDisableTiming);

    cudaEventRecord(ev_fork, 0);
    cudaStreamWaitEvent(s2, ev_fork, 0);
    csr_build<<<NBLK, CBS, 0, s2>>>(ei, E, N);                                  // 0
    cudaEventRecord(ev_join, s2);

    prep_w<<<64, 256>>>(W, (unsigned char*)p_whi, (unsigned char*)p_wlo);       // 1
    prep_w<<<64, 256>>>(lin_w, (unsigned char*)p_lwhi, (unsigned char*)p_lwlo); // 2
    gemm_mma<0><<<gemm_blocks, 256, SMEM>>>(                                    // 3 <- profiled
        x, (const unsigned char*)p_whi, (const unsigned char*)p_wlo,
        att_s, att_d, (float*)p_h, N);

    cudaStreamWaitEvent(0, ev_join, 0);
    gather_kernel<<<(N * 32 + 255) / 256, 256>>>(N);                            // 4
    gemm_mma<1><<<gemm_blocks, 256, SMEM>>>(                                    // 5
        (const float*)p_acc, (const unsigned char*)p_lwhi, (const unsigned char*)p_lwlo,
        lin_b, nullptr, out, N);
}